// round 8
// baseline (speedup 1.0000x reference)
#include <cuda_runtime.h>
#include <cuda_bf16.h>

#define KOBJ 512
#define MAXN 131072
#define EPSF 1e-9f
#define HPB  136      // 80000/136 -> 589 blocks (~1 wave of 4x512 blocks/SM)
#define NSLOT 16      // atomic slot spreading factor

// ---------------- device scratch (no allocations allowed) ----------------
__device__ unsigned long long g_key[KOBJ * NSLOT];
__device__ float g_cnt[KOBJ * NSLOT], g_num[KOBJ * NSLOT], g_den[KOBJ * NSLOT];
__device__ float g_att[KOBJ * NSLOT], g_rep[KOBJ * NSLOT];
__device__ float g_cntc[KOBJ], g_numc[KOBJ], g_denc[KOBJ];
__device__ float g_xa[KOBJ], g_ya[KOBJ], g_qa[KOBJ], g_ba[KOBJ];
__device__ float g_noise_sum, g_noise_cnt, g_cc2;
__device__ unsigned g_ctrB;
__device__ float4 g_hit[MAXN];   // {x, y, q, t_idx(as float bits)}

// ---------------- helpers ----------------
__device__ __forceinline__ float fsqrt_approx(float x) {
    float y; asm("sqrt.approx.f32 %0, %1;" : "=f"(y) : "f"(x)); return y;
}
__device__ __forceinline__ float softclip(float x, float a) {
    float s = x / a;
    s = (s > 1.0f) ? __logf(s + 1.0f) : s;
    return s * a;
}
__device__ __forceinline__ float huber(float x, float d) {
    float ax = fabsf(x);
    return (ax < d) ? x * x : (d * d + 2.0f * d * (ax - d));
}

// ================= kernel A: per-hit pass (slot-spread atomics) =============
__global__ __launch_bounds__(256) void k_hits(
        const float* __restrict__ pb,  const float* __restrict__ cc,
        const float* __restrict__ pe,  const float* __restrict__ pp,
        const float* __restrict__ pt,  const float* __restrict__ pid,
        const int*   __restrict__ tix, const float* __restrict__ te,
        const float* __restrict__ tp,  const float* __restrict__ tt,
        int n)
{
    int i = blockIdx.x * blockDim.x + threadIdx.x;
    int slot = blockIdx.x & (NSLOT - 1);
    float cc2 = 0.f, nsum = 0.f, ncnt = 0.f;
    if (i < n) {
        float b  = fminf(fmaxf(pb[i], 1e-6f), 1.0f - 1e-6f);
        float at = 0.5f * __logf(__fdividef(1.0f + b, 1.0f - b));   // atanh(b)
        float q  = at * at + 0.1f;                                   // + Q_MIN
        float x = cc[2 * i], y = cc[2 * i + 1];
        cc2 = x * x + y * y;
        int t = tix[i];
        float4 h; h.x = x; h.y = y; h.z = q; h.w = __int_as_float(t);
        g_hit[i] = h;

        if (t < 0) {
            nsum = b; ncnt = 1.0f;
        } else {
            int ts = t * NSLOT + slot;
            atomicAdd(&g_cnt[ts], 1.0f);
            // argmax beta, ties -> lowest index (matches jnp.argmax)
            unsigned long long key =
                ((unsigned long long)__float_as_uint(b) << 32) |
                (unsigned long long)(0xFFFFFFFFu - (unsigned)i);
            atomicMax(&g_key[ts], key);

            // payload losses
            float tei = te[i];
            float ed  = fabsf(tei - pe[i]);
            float el  = softclip(10.0f * __expf(-0.1f * ed * ed) + 0.01f * ed, 10.0f);

            float dpx = tp[2 * i]     - pp[2 * i];
            float dpy = tp[2 * i + 1] - pp[2 * i + 1];
            float d2p = dpx * dpx + dpy * dpy;
            float pl  = softclip(huber(fsqrt_approx(d2p * 0.01f + 0.01f), 10.0f), 3.0f);

            float tl  = softclip(huber(tt[i] - pt[i], 2.0f), 6.0f);

            float cl = 0.f;
            #pragma unroll
            for (int j = 0; j < 6; j++) { float v = pid[6 * i + j]; cl += v * v; }
            cl *= (1e-8f / 6.0f);

            float payload = el + pl + tl + cl;
            float ew = (tei > 10.0f) ? 1.0f : (tei - 0.5f) * (1.0f / 9.5f);
            ew = fmaxf(ew, 0.0f);
            float pw = b * ew;
            atomicAdd(&g_num[ts], payload * pw);
            atomicAdd(&g_den[ts], pw);
        }
    }
    // warp-aggregate scalar sums -> 1 atomic per warp each
    #pragma unroll
    for (int o = 16; o; o >>= 1) {
        cc2  += __shfl_down_sync(0xFFFFFFFFu, cc2,  o);
        nsum += __shfl_down_sync(0xFFFFFFFFu, nsum, o);
        ncnt += __shfl_down_sync(0xFFFFFFFFu, ncnt, o);
    }
    if ((threadIdx.x & 31) == 0) {
        atomicAdd(&g_cc2, cc2);
        if (nsum != 0.f) atomicAdd(&g_noise_sum, nsum);
        if (ncnt != 0.f) atomicAdd(&g_noise_cnt, ncnt);
    }
}

// ====== kernel B: slot reduce + alpha gather (1 block, 512 threads) =========
__global__ __launch_bounds__(KOBJ) void k_mid(const float* __restrict__ pb,
                                              const float* __restrict__ cc) {
    int k = threadIdx.x;
    float c = 0.f, nm = 0.f, dn = 0.f;
    unsigned long long key = 0ull;
    #pragma unroll
    for (int s = 0; s < NSLOT; s++) {
        int ts = k * NSLOT + s;
        c  += g_cnt[ts];
        nm += g_num[ts];
        dn += g_den[ts];
        unsigned long long kk = g_key[ts];
        key = (kk > key) ? kk : key;
    }
    g_cntc[k] = c; g_numc[k] = nm; g_denc[k] = dn;

    if (c > 0.f) {
        unsigned enc = (unsigned)(key & 0xFFFFFFFFull);
        int a = (int)(0xFFFFFFFFu - enc);
        float b  = fminf(fmaxf(pb[a], 1e-6f), 1.0f - 1e-6f);
        float at = 0.5f * __logf(__fdividef(1.0f + b, 1.0f - b));
        g_qa[k] = at * at + 0.1f;
        g_xa[k] = cc[2 * a];
        g_ya[k] = cc[2 * a + 1];
        g_ba[k] = b;
    } else {
        g_qa[k] = 0.f; g_xa[k] = 1e18f; g_ya[k] = 0.f; g_ba[k] = 0.f;
    }
}

// ======== kernel C: branchless pair pass + (last block) final reduce ========
__global__ __launch_bounds__(512, 4) void k_pairs(float* __restrict__ out,
                                                  int n, int out_size) {
    int k = threadIdx.x;
    int slot = blockIdx.x & (NSLOT - 1);
    float ax = g_xa[k], ay = g_ya[k], qa = g_qa[k];
    int s = blockIdx.x * HPB;
    int m = min(n - s, HPB);
    __shared__ float4 sh[HPB];
    if (k < m) sh[k] = g_hit[s + k];
    __syncthreads();

    // pure repulsion over ALL pairs in stripe (membership handled below)
    float ar0 = 0.f, ar1 = 0.f;
    if (m == HPB) {
        #pragma unroll
        for (int i = 0; i < HPB; i += 2) {
            {
                float4 h = sh[i];
                float dx = h.x - ax, dy = h.y - ay;
                float d2 = fmaf(dx, dx, 1e-6f);
                d2 = fmaf(dy, dy, d2);
                float w = 1.0f - fsqrt_approx(d2);
                ar0 = fmaf(fmaxf(w, 0.f), h.z, ar0);
            }
            {
                float4 h = sh[i + 1];
                float dx = h.x - ax, dy = h.y - ay;
                float d2 = fmaf(dx, dx, 1e-6f);
                d2 = fmaf(dy, dy, d2);
                float w = 1.0f - fsqrt_approx(d2);
                ar1 = fmaf(fmaxf(w, 0.f), h.z, ar1);
            }
        }
    } else {
        for (int i = 0; i < m; i++) {
            float4 h = sh[i];
            float dx = h.x - ax, dy = h.y - ay;
            float d2 = fmaf(dx, dx, 1e-6f);
            d2 = fmaf(dy, dy, d2);
            float w = 1.0f - fsqrt_approx(d2);
            ar0 = fmaf(fmaxf(w, 0.f), h.z, ar0);
        }
    }
    atomicAdd(&g_rep[k * NSLOT + slot], (ar0 + ar1) * qa);

    // O(N) side path: attraction + subtract member's repulsion hinge
    if (k < m) {
        float4 h = sh[k];
        int t = __float_as_int(h.w);
        if (t >= 0) {
            float axt = g_xa[t], ayt = g_ya[t], qat = g_qa[t];
            float dx = h.x - axt, dy = h.y - ayt;
            float d2  = dx * dx + dy * dy;
            float d2e = fmaf(dx, dx, 1e-6f); d2e = fmaf(dy, dy, d2e);
            float wm  = fmaxf(1.0f - fsqrt_approx(d2e), 0.f);
            atomicAdd(&g_att[t * NSLOT + slot],  d2 * h.z * qat);
            atomicAdd(&g_rep[t * NSLOT + slot], -wm * h.z * qat);
        }
    }

    // ---- last-block final reduce + scratch re-zero for next replay ----
    __threadfence();
    __syncthreads();
    __shared__ unsigned s_last;
    if (k == 0) s_last = (atomicAdd(&g_ctrB, 1u) == gridDim.x - 1u);
    __syncthreads();
    if (!s_last) return;

    float att = 0.f, rep = 0.f;
    #pragma unroll
    for (int sl = 0; sl < NSLOT; sl++) {
        att += g_att[k * NSLOT + sl];
        rep += g_rep[k * NSLOT + sl];
    }
    float c  = g_cntc[k];
    bool  hh = c > 0.f;
    float la = hh ? att / (c + EPSF) : 0.f;
    float lr = hh ? rep / ((float)n - c + EPSF) : 0.f;
    float lp = hh ? g_numc[k] / (g_denc[k] + EPSF) : 0.f;
    float lb = hh ? (1.0f - g_ba[k]) : 0.f;
    float no = hh ? 1.0f : 0.f;
    float nse = g_noise_sum, nsc = g_noise_cnt, ccs = g_cc2;

    // re-zero everything for the next graph replay
    #pragma unroll
    for (int sl = 0; sl < NSLOT; sl++) {
        int ts = k * NSLOT + sl;
        g_key[ts] = 0ull;
        g_cnt[ts] = 0.f; g_num[ts] = 0.f; g_den[ts] = 0.f;
        g_att[ts] = 0.f; g_rep[ts] = 0.f;
    }
    if (k == 0) { g_noise_sum = 0.f; g_noise_cnt = 0.f; g_cc2 = 0.f; g_ctrB = 0u; }

    __shared__ float red[5][16];
    float v[5] = {la, lr, lp, lb, no};
    int lane = k & 31, w = k >> 5;
    #pragma unroll
    for (int j = 0; j < 5; j++) {
        float t = v[j];
        #pragma unroll
        for (int o = 16; o; o >>= 1) t += __shfl_down_sync(0xFFFFFFFFu, t, o);
        if (lane == 0) red[j][w] = t;
    }
    __syncthreads();
    if (k == 0) {
        float acc[5] = {0.f, 0.f, 0.f, 0.f, 0.f};
        #pragma unroll
        for (int w2 = 0; w2 < 16; w2++)
            #pragma unroll
            for (int j = 0; j < 5; j++) acc[j] += red[j][w2];
        float nobj = acc[4] + EPSF;
        float total = (acc[0] + acc[1] + acc[2] + acc[3]) / nobj
                    + nse / (nsc + EPSF)
                    + 0.001f * ccs / ((float)n * 2.0f);
        for (int i = 0; i < out_size; i++) out[i] = total;
    }
}

// ---------------- launch ----------------
extern "C" void kernel_launch(void* const* d_in, const int* in_sizes, int n_in,
                              void* d_out, int out_size) {
    const float* pb  = (const float*)d_in[0];   // pred_beta    (N,1)
    const float* cc  = (const float*)d_in[1];   // pred_ccoords (N,2)
    const float* pe  = (const float*)d_in[2];   // pred_energy  (N,1)
    const float* pp  = (const float*)d_in[3];   // pred_pos     (N,2)
    const float* pt  = (const float*)d_in[4];   // pred_time    (N,1)
    const float* pid = (const float*)d_in[5];   // pred_id      (N,6)
    const int*   tix = (const int*)  d_in[6];   // t_idx        (N,1)
    const float* te  = (const float*)d_in[7];   // t_energy     (N,1)
    const float* tp  = (const float*)d_in[8];   // t_pos        (N,2)
    const float* tt  = (const float*)d_in[9];   // t_time       (N,1)
    // d_in[10] = t_pid, unused by the reference loss

    int n = in_sizes[0];

    k_hits<<<(n + 255) / 256, 256>>>(pb, cc, pe, pp, pt, pid, tix, te, tp, tt, n);
    k_mid<<<1, KOBJ>>>(pb, cc);
    k_pairs<<<(n + HPB - 1) / HPB, KOBJ>>>((float*)d_out, n, out_size);
}

// round 9
// speedup vs baseline: 1.0670x; 1.0670x over previous
#include <cuda_runtime.h>
#include <cuda_bf16.h>

#define KOBJ 512
#define MAXN 131072
#define EPSF 1e-9f
#define HPB  136      // 80000/136 -> 589 blocks (~1 wave of 4x512 blocks/SM)
#define NSLOT 16      // atomic slot spreading factor

// ---------------- device scratch (no allocations allowed) ----------------
__device__ unsigned long long g_key[KOBJ * NSLOT];
__device__ float g_cnt[KOBJ * NSLOT], g_num[KOBJ * NSLOT], g_den[KOBJ * NSLOT];
__device__ float g_att[KOBJ * NSLOT], g_rep[KOBJ * NSLOT];
__device__ float g_cntc[KOBJ], g_numc[KOBJ], g_denc[KOBJ];
__device__ float g_xa[KOBJ], g_ya[KOBJ], g_qa[KOBJ], g_ba[KOBJ];
__device__ float g_noise_sum, g_noise_cnt, g_cc2;
__device__ unsigned g_ctrA, g_ctrB;
__device__ float4 g_hit[MAXN];   // {x, y, q, t_idx(as float bits)}

// ---------------- helpers ----------------
__device__ __forceinline__ float fsqrt_approx(float x) {
    float y; asm("sqrt.approx.f32 %0, %1;" : "=f"(y) : "f"(x)); return y;
}
__device__ __forceinline__ float softclip(float x, float a) {
    float s = x / a;
    s = (s > 1.0f) ? __logf(s + 1.0f) : s;
    return s * a;
}
__device__ __forceinline__ float huber(float x, float d) {
    float ax = fabsf(x);
    return (ax < d) ? x * x : (d * d + 2.0f * d * (ax - d));
}

// ===== kernel A: per-hit pass (slot-spread atomics) + last-block gather =====
// Early blocks also zero g_att/g_rep for THIS replay's k_pairs (k_hits never
// touches them, and k_hits fully precedes k_pairs in stream order).
__global__ __launch_bounds__(256) void k_hits(
        const float* __restrict__ pb,  const float* __restrict__ cc,
        const float* __restrict__ pe,  const float* __restrict__ pp,
        const float* __restrict__ pt,  const float* __restrict__ pid,
        const int*   __restrict__ tix, const float* __restrict__ te,
        const float* __restrict__ tp,  const float* __restrict__ tt,
        int n)
{
    // distributed zeroing of pair-pass accumulators (overlapped, off critical path)
    if (blockIdx.x < 32) {
        int base = blockIdx.x * blockDim.x + threadIdx.x;           // 8192 threads
        for (int j = base; j < KOBJ * NSLOT; j += 32 * 256) {
            g_att[j] = 0.f; g_rep[j] = 0.f;
        }
    }

    int i = blockIdx.x * blockDim.x + threadIdx.x;
    int slot = blockIdx.x & (NSLOT - 1);
    float cc2 = 0.f, nsum = 0.f, ncnt = 0.f;
    if (i < n) {
        float b  = fminf(fmaxf(pb[i], 1e-6f), 1.0f - 1e-6f);
        float at = 0.5f * __logf(__fdividef(1.0f + b, 1.0f - b));   // atanh(b)
        float q  = at * at + 0.1f;                                   // + Q_MIN
        float x = cc[2 * i], y = cc[2 * i + 1];
        cc2 = x * x + y * y;
        int t = tix[i];
        float4 h; h.x = x; h.y = y; h.z = q; h.w = __int_as_float(t);
        g_hit[i] = h;

        if (t < 0) {
            nsum = b; ncnt = 1.0f;
        } else {
            int ts = t * NSLOT + slot;
            atomicAdd(&g_cnt[ts], 1.0f);
            // argmax beta, ties -> lowest index (matches jnp.argmax)
            unsigned long long key =
                ((unsigned long long)__float_as_uint(b) << 32) |
                (unsigned long long)(0xFFFFFFFFu - (unsigned)i);
            atomicMax(&g_key[ts], key);

            // payload losses
            float tei = te[i];
            float ed  = fabsf(tei - pe[i]);
            float el  = softclip(10.0f * __expf(-0.1f * ed * ed) + 0.01f * ed, 10.0f);

            float dpx = tp[2 * i]     - pp[2 * i];
            float dpy = tp[2 * i + 1] - pp[2 * i + 1];
            float d2p = dpx * dpx + dpy * dpy;
            float pl  = softclip(huber(fsqrt_approx(d2p * 0.01f + 0.01f), 10.0f), 3.0f);

            float tl  = softclip(huber(tt[i] - pt[i], 2.0f), 6.0f);

            float cl = 0.f;
            #pragma unroll
            for (int j = 0; j < 6; j++) { float v = pid[6 * i + j]; cl += v * v; }
            cl *= (1e-8f / 6.0f);

            float payload = el + pl + tl + cl;
            float ew = (tei > 10.0f) ? 1.0f : (tei - 0.5f) * (1.0f / 9.5f);
            ew = fmaxf(ew, 0.0f);
            float pw = b * ew;
            atomicAdd(&g_num[ts], payload * pw);
            atomicAdd(&g_den[ts], pw);
        }
    }
    // warp-aggregate scalar sums -> 1 atomic per warp each
    #pragma unroll
    for (int o = 16; o; o >>= 1) {
        cc2  += __shfl_down_sync(0xFFFFFFFFu, cc2,  o);
        nsum += __shfl_down_sync(0xFFFFFFFFu, nsum, o);
        ncnt += __shfl_down_sync(0xFFFFFFFFu, ncnt, o);
    }
    if ((threadIdx.x & 31) == 0) {
        atomicAdd(&g_cc2, cc2);
        if (nsum != 0.f) atomicAdd(&g_noise_sum, nsum);
        if (ncnt != 0.f) atomicAdd(&g_noise_cnt, ncnt);
    }

    // ---- last-block: slot reduce + alpha gather ----
    __threadfence();
    __syncthreads();
    __shared__ unsigned s_last;
    if (threadIdx.x == 0) s_last = (atomicAdd(&g_ctrA, 1u) == gridDim.x - 1u);
    __syncthreads();
    if (!s_last) return;
    if (threadIdx.x == 0) g_ctrA = 0u;

    for (int k = threadIdx.x; k < KOBJ; k += blockDim.x) {
        float c = 0.f, nm = 0.f, dn = 0.f;
        unsigned long long key = 0ull;
        #pragma unroll
        for (int sl = 0; sl < NSLOT; sl++) {
            int ts = k * NSLOT + sl;
            c  += g_cnt[ts];
            nm += g_num[ts];
            dn += g_den[ts];
            unsigned long long kk = g_key[ts];
            key = (kk > key) ? kk : key;
        }
        g_cntc[k] = c; g_numc[k] = nm; g_denc[k] = dn;

        if (c > 0.f) {
            unsigned enc = (unsigned)(key & 0xFFFFFFFFull);
            int a = (int)(0xFFFFFFFFu - enc);
            float b  = fminf(fmaxf(pb[a], 1e-6f), 1.0f - 1e-6f);
            float at = 0.5f * __logf(__fdividef(1.0f + b, 1.0f - b));
            g_qa[k] = at * at + 0.1f;
            g_xa[k] = cc[2 * a];
            g_ya[k] = cc[2 * a + 1];
            g_ba[k] = b;
        } else {
            g_qa[k] = 0.f; g_xa[k] = 1e18f; g_ya[k] = 0.f; g_ba[k] = 0.f;
        }
    }
}

// ======== kernel B: branchless pair pass + (last block) final reduce ========
__global__ __launch_bounds__(512, 4) void k_pairs(float* __restrict__ out,
                                                  int n, int out_size) {
    int k = threadIdx.x;
    int slot = blockIdx.x & (NSLOT - 1);
    float ax = g_xa[k], ay = g_ya[k], qa = g_qa[k];
    int s = blockIdx.x * HPB;
    int m = min(n - s, HPB);
    __shared__ float4 sh[HPB];
    if (k < m) sh[k] = g_hit[s + k];
    __syncthreads();

    // pure repulsion over ALL pairs in stripe (membership handled below)
    float ar = 0.f;
    if (m == HPB) {
        #pragma unroll 8
        for (int i = 0; i < HPB; i++) {
            float4 h = sh[i];
            float dx = h.x - ax, dy = h.y - ay;
            float d2 = fmaf(dx, dx, 1e-6f);
            d2 = fmaf(dy, dy, d2);
            float w = 1.0f - fsqrt_approx(d2);
            ar = fmaf(fmaxf(w, 0.f), h.z, ar);
        }
    } else {
        for (int i = 0; i < m; i++) {
            float4 h = sh[i];
            float dx = h.x - ax, dy = h.y - ay;
            float d2 = fmaf(dx, dx, 1e-6f);
            d2 = fmaf(dy, dy, d2);
            float w = 1.0f - fsqrt_approx(d2);
            ar = fmaf(fmaxf(w, 0.f), h.z, ar);
        }
    }
    atomicAdd(&g_rep[k * NSLOT + slot], ar * qa);

    // O(N) side path: attraction + subtract member's repulsion hinge
    if (k < m) {
        float4 h = sh[k];
        int t = __float_as_int(h.w);
        if (t >= 0) {
            float axt = g_xa[t], ayt = g_ya[t], qat = g_qa[t];
            float dx = h.x - axt, dy = h.y - ayt;
            float d2  = dx * dx + dy * dy;
            float d2e = fmaf(dx, dx, 1e-6f); d2e = fmaf(dy, dy, d2e);
            float wm  = fmaxf(1.0f - fsqrt_approx(d2e), 0.f);
            atomicAdd(&g_att[t * NSLOT + slot],  d2 * h.z * qat);
            atomicAdd(&g_rep[t * NSLOT + slot], -wm * h.z * qat);
        }
    }

    // ---- last-block final reduce + zero the hit-pass scratch for next replay ----
    __threadfence();
    __syncthreads();
    __shared__ unsigned s_last;
    if (k == 0) s_last = (atomicAdd(&g_ctrB, 1u) == gridDim.x - 1u);
    __syncthreads();
    if (!s_last) return;

    float att = 0.f, rep = 0.f;
    #pragma unroll
    for (int sl = 0; sl < NSLOT; sl++) {
        att += g_att[k * NSLOT + sl];
        rep += g_rep[k * NSLOT + sl];
    }
    float c  = g_cntc[k];
    bool  hh = c > 0.f;
    float la = hh ? att / (c + EPSF) : 0.f;
    float lr = hh ? rep / ((float)n - c + EPSF) : 0.f;
    float lp = hh ? g_numc[k] / (g_denc[k] + EPSF) : 0.f;
    float lb = hh ? (1.0f - g_ba[k]) : 0.f;
    float no = hh ? 1.0f : 0.f;
    float nse = g_noise_sum, nsc = g_noise_cnt, ccs = g_cc2;

    // zero hit-pass scratch for next replay (att/rep are zeroed by next k_hits)
    #pragma unroll
    for (int sl = 0; sl < NSLOT; sl++) {
        int ts = k * NSLOT + sl;
        g_key[ts] = 0ull;
        g_cnt[ts] = 0.f; g_num[ts] = 0.f; g_den[ts] = 0.f;
    }
    if (k == 0) { g_noise_sum = 0.f; g_noise_cnt = 0.f; g_cc2 = 0.f; g_ctrB = 0u; }

    __shared__ float red[5][16];
    float v[5] = {la, lr, lp, lb, no};
    int lane = k & 31, w = k >> 5;
    #pragma unroll
    for (int j = 0; j < 5; j++) {
        float t = v[j];
        #pragma unroll
        for (int o = 16; o; o >>= 1) t += __shfl_down_sync(0xFFFFFFFFu, t, o);
        if (lane == 0) red[j][w] = t;
    }
    __syncthreads();
    if (k == 0) {
        float acc[5] = {0.f, 0.f, 0.f, 0.f, 0.f};
        #pragma unroll
        for (int w2 = 0; w2 < 16; w2++)
            #pragma unroll
            for (int j = 0; j < 5; j++) acc[j] += red[j][w2];
        float nobj = acc[4] + EPSF;
        float total = (acc[0] + acc[1] + acc[2] + acc[3]) / nobj
                    + nse / (nsc + EPSF)
                    + 0.001f * ccs / ((float)n * 2.0f);
        for (int i = 0; i < out_size; i++) out[i] = total;
    }
}

// ---------------- launch ----------------
extern "C" void kernel_launch(void* const* d_in, const int* in_sizes, int n_in,
                              void* d_out, int out_size) {
    const float* pb  = (const float*)d_in[0];   // pred_beta    (N,1)
    const float* cc  = (const float*)d_in[1];   // pred_ccoords (N,2)
    const float* pe  = (const float*)d_in[2];   // pred_energy  (N,1)
    const float* pp  = (const float*)d_in[3];   // pred_pos     (N,2)
    const float* pt  = (const float*)d_in[4];   // pred_time    (N,1)
    const float* pid = (const float*)d_in[5];   // pred_id      (N,6)
    const int*   tix = (const int*)  d_in[6];   // t_idx        (N,1)
    const float* te  = (const float*)d_in[7];   // t_energy     (N,1)
    const float* tp  = (const float*)d_in[8];   // t_pos        (N,2)
    const float* tt  = (const float*)d_in[9];   // t_time       (N,1)
    // d_in[10] = t_pid, unused by the reference loss

    int n = in_sizes[0];

    k_hits<<<(n + 255) / 256, 256>>>(pb, cc, pe, pp, pt, pid, tix, te, tp, tt, n);
    k_pairs<<<(n + HPB - 1) / HPB, KOBJ>>>((float*)d_out, n, out_size);
}

// round 10
// speedup vs baseline: 1.4858x; 1.3926x over previous
#include <cuda_runtime.h>
#include <cuda_bf16.h>

#define KOBJ 512
#define MAXN 131072
#define EPSF 1e-9f
#define HPB  136      // 80000/136 -> 589 blocks (~1 wave of 4x512 blocks/SM)
#define NSLOT 16      // atomic slot spreading (hit pass only)

// ---------------- device scratch (no allocations allowed) ----------------
__device__ unsigned long long g_key[KOBJ * NSLOT];
__device__ float g_cnt[KOBJ * NSLOT], g_num[KOBJ * NSLOT], g_den[KOBJ * NSLOT];
__device__ float g_att[KOBJ], g_rep[KOBJ];
__device__ float g_cntc[KOBJ], g_numc[KOBJ], g_denc[KOBJ];
__device__ float g_xa[KOBJ], g_ya[KOBJ], g_qa[KOBJ], g_ba[KOBJ];
__device__ float g_noise_sum, g_noise_cnt, g_cc2;
__device__ unsigned g_ctrA, g_ctrB;
__device__ float4 g_hit[MAXN];   // {x, y, q, t_idx(as float bits)}

// ---------------- helpers ----------------
__device__ __forceinline__ float fsqrt_approx(float x) {
    float y; asm("sqrt.approx.f32 %0, %1;" : "=f"(y) : "f"(x)); return y;
}
__device__ __forceinline__ float softclip(float x, float a) {
    float s = x / a;
    s = (s > 1.0f) ? __logf(s + 1.0f) : s;
    return s * a;
}
__device__ __forceinline__ float huber(float x, float d) {
    float ax = fabsf(x);
    return (ax < d) ? x * x : (d * d + 2.0f * d * (ax - d));
}

// ===== kernel A: per-hit pass (slot-spread atomics) + last-block gather =====
__global__ __launch_bounds__(256) void k_hits(
        const float* __restrict__ pb,  const float* __restrict__ cc,
        const float* __restrict__ pe,  const float* __restrict__ pp,
        const float* __restrict__ pt,  const float* __restrict__ pid,
        const int*   __restrict__ tix, const float* __restrict__ te,
        const float* __restrict__ tp,  const float* __restrict__ tt,
        int n)
{
    int i = blockIdx.x * blockDim.x + threadIdx.x;
    int slot = blockIdx.x & (NSLOT - 1);
    float cc2 = 0.f, nsum = 0.f, ncnt = 0.f;
    if (i < n) {
        float b  = fminf(fmaxf(pb[i], 1e-6f), 1.0f - 1e-6f);
        float at = 0.5f * __logf(__fdividef(1.0f + b, 1.0f - b));   // atanh(b)
        float q  = at * at + 0.1f;                                   // + Q_MIN
        float x = cc[2 * i], y = cc[2 * i + 1];
        cc2 = x * x + y * y;
        int t = tix[i];
        float4 h; h.x = x; h.y = y; h.z = q; h.w = __int_as_float(t);
        g_hit[i] = h;

        if (t < 0) {
            nsum = b; ncnt = 1.0f;
        } else {
            int ts = t * NSLOT + slot;
            atomicAdd(&g_cnt[ts], 1.0f);
            // argmax beta, ties -> lowest index (matches jnp.argmax)
            unsigned long long key =
                ((unsigned long long)__float_as_uint(b) << 32) |
                (unsigned long long)(0xFFFFFFFFu - (unsigned)i);
            atomicMax(&g_key[ts], key);

            // payload losses
            float tei = te[i];
            float ed  = fabsf(tei - pe[i]);
            float el  = softclip(10.0f * __expf(-0.1f * ed * ed) + 0.01f * ed, 10.0f);

            float dpx = tp[2 * i]     - pp[2 * i];
            float dpy = tp[2 * i + 1] - pp[2 * i + 1];
            float d2p = dpx * dpx + dpy * dpy;
            float pl  = softclip(huber(fsqrt_approx(d2p * 0.01f + 0.01f), 10.0f), 3.0f);

            float tl  = softclip(huber(tt[i] - pt[i], 2.0f), 6.0f);

            float cl = 0.f;
            #pragma unroll
            for (int j = 0; j < 6; j++) { float v = pid[6 * i + j]; cl += v * v; }
            cl *= (1e-8f / 6.0f);

            float payload = el + pl + tl + cl;
            float ew = (tei > 10.0f) ? 1.0f : (tei - 0.5f) * (1.0f / 9.5f);
            ew = fmaxf(ew, 0.0f);
            float pw = b * ew;
            atomicAdd(&g_num[ts], payload * pw);
            atomicAdd(&g_den[ts], pw);
        }
    }
    // warp-aggregate scalar sums -> 1 atomic per warp each
    #pragma unroll
    for (int o = 16; o; o >>= 1) {
        cc2  += __shfl_down_sync(0xFFFFFFFFu, cc2,  o);
        nsum += __shfl_down_sync(0xFFFFFFFFu, nsum, o);
        ncnt += __shfl_down_sync(0xFFFFFFFFu, ncnt, o);
    }
    if ((threadIdx.x & 31) == 0) {
        atomicAdd(&g_cc2, cc2);
        if (nsum != 0.f) atomicAdd(&g_noise_sum, nsum);
        if (ncnt != 0.f) atomicAdd(&g_noise_cnt, ncnt);
    }

    // ---- last-block: slot reduce + alpha gather ----
    __threadfence();
    __syncthreads();
    __shared__ unsigned s_last;
    if (threadIdx.x == 0) s_last = (atomicAdd(&g_ctrA, 1u) == gridDim.x - 1u);
    __syncthreads();
    if (!s_last) return;
    if (threadIdx.x == 0) g_ctrA = 0u;

    for (int k = threadIdx.x; k < KOBJ; k += blockDim.x) {
        float c = 0.f, nm = 0.f, dn = 0.f;
        unsigned long long key = 0ull;
        #pragma unroll
        for (int sl = 0; sl < NSLOT; sl++) {
            int ts = k * NSLOT + sl;
            c  += g_cnt[ts];
            nm += g_num[ts];
            dn += g_den[ts];
            unsigned long long kk = g_key[ts];
            key = (kk > key) ? kk : key;
        }
        g_cntc[k] = c; g_numc[k] = nm; g_denc[k] = dn;

        if (c > 0.f) {
            unsigned enc = (unsigned)(key & 0xFFFFFFFFull);
            int a = (int)(0xFFFFFFFFu - enc);
            float b  = fminf(fmaxf(pb[a], 1e-6f), 1.0f - 1e-6f);
            float at = 0.5f * __logf(__fdividef(1.0f + b, 1.0f - b));
            g_qa[k] = at * at + 0.1f;
            g_xa[k] = cc[2 * a];
            g_ya[k] = cc[2 * a + 1];
            g_ba[k] = b;
        } else {
            g_qa[k] = 0.f; g_xa[k] = 1e18f; g_ya[k] = 0.f; g_ba[k] = 0.f;
        }
    }
}

// ======== kernel B: branchless pair pass + (last block) final reduce ========
// Hot loop + atomics identical to the measured-27.2us version.
__global__ __launch_bounds__(512, 4) void k_pairs(float* __restrict__ out,
                                                  int n, int out_size) {
    int k = threadIdx.x;

    // distributed zeroing of the (now dead) hit-pass slot arrays for the next
    // replay; k_hits of the next replay is stream-ordered after us.
    if (blockIdx.x < 32) {
        int base = blockIdx.x * 512 + k;                 // 16384 threads
        for (int j = base; j < KOBJ * NSLOT; j += 32 * 512) {
            g_key[j] = 0ull;
            g_cnt[j] = 0.f; g_num[j] = 0.f; g_den[j] = 0.f;
        }
    }

    float ax = g_xa[k], ay = g_ya[k], qa = g_qa[k];
    int s = blockIdx.x * HPB;
    int m = min(n - s, HPB);
    __shared__ float4 sh[HPB];
    if (k < m) sh[k] = g_hit[s + k];
    __syncthreads();

    // pure repulsion over ALL pairs in stripe (membership handled below)
    float ar = 0.f;
    if (m == HPB) {
        #pragma unroll 8
        for (int i = 0; i < HPB; i++) {
            float4 h = sh[i];
            float dx = h.x - ax, dy = h.y - ay;
            float d2 = fmaf(dx, dx, 1e-6f);
            d2 = fmaf(dy, dy, d2);
            float w = 1.0f - fsqrt_approx(d2);
            ar = fmaf(fmaxf(w, 0.f), h.z, ar);
        }
    } else {
        for (int i = 0; i < m; i++) {
            float4 h = sh[i];
            float dx = h.x - ax, dy = h.y - ay;
            float d2 = fmaf(dx, dx, 1e-6f);
            d2 = fmaf(dy, dy, d2);
            float w = 1.0f - fsqrt_approx(d2);
            ar = fmaf(fmaxf(w, 0.f), h.z, ar);
        }
    }
    atomicAdd(&g_rep[k], ar * qa);

    // O(N) side path: attraction + subtract member's repulsion hinge
    if (k < m) {
        float4 h = sh[k];
        int t = __float_as_int(h.w);
        if (t >= 0) {
            float axt = g_xa[t], ayt = g_ya[t], qat = g_qa[t];
            float dx = h.x - axt, dy = h.y - ayt;
            float d2  = dx * dx + dy * dy;
            float d2e = fmaf(dx, dx, 1e-6f); d2e = fmaf(dy, dy, d2e);
            float wm  = fmaxf(1.0f - fsqrt_approx(d2e), 0.f);
            atomicAdd(&g_att[t],  d2 * h.z * qat);
            atomicAdd(&g_rep[t], -wm * h.z * qat);
        }
    }

    // ---- last-block final reduce + zero small scratch for next replay ----
    __threadfence();
    __syncthreads();
    __shared__ unsigned s_last;
    if (k == 0) s_last = (atomicAdd(&g_ctrB, 1u) == gridDim.x - 1u);
    __syncthreads();
    if (!s_last) return;

    float c  = g_cntc[k];
    bool  hh = c > 0.f;
    float la = hh ? g_att[k] / (c + EPSF) : 0.f;
    float lr = hh ? g_rep[k] / ((float)n - c + EPSF) : 0.f;
    float lp = hh ? g_numc[k] / (g_denc[k] + EPSF) : 0.f;
    float lb = hh ? (1.0f - g_ba[k]) : 0.f;
    float no = hh ? 1.0f : 0.f;
    float nse = g_noise_sum, nsc = g_noise_cnt, ccs = g_cc2;

    // re-zero small per-object accumulators + scalars for the next replay
    g_att[k] = 0.f; g_rep[k] = 0.f;
    if (k == 0) { g_noise_sum = 0.f; g_noise_cnt = 0.f; g_cc2 = 0.f; g_ctrB = 0u; }

    __shared__ float red[5][16];
    float v[5] = {la, lr, lp, lb, no};
    int lane = k & 31, w = k >> 5;
    #pragma unroll
    for (int j = 0; j < 5; j++) {
        float t = v[j];
        #pragma unroll
        for (int o = 16; o; o >>= 1) t += __shfl_down_sync(0xFFFFFFFFu, t, o);
        if (lane == 0) red[j][w] = t;
    }
    __syncthreads();
    if (k == 0) {
        float acc[5] = {0.f, 0.f, 0.f, 0.f, 0.f};
        #pragma unroll
        for (int w2 = 0; w2 < 16; w2++)
            #pragma unroll
            for (int j = 0; j < 5; j++) acc[j] += red[j][w2];
        float nobj = acc[4] + EPSF;
        float total = (acc[0] + acc[1] + acc[2] + acc[3]) / nobj
                    + nse / (nsc + EPSF)
                    + 0.001f * ccs / ((float)n * 2.0f);
        for (int i = 0; i < out_size; i++) out[i] = total;
    }
}

// ---------------- launch ----------------
extern "C" void kernel_launch(void* const* d_in, const int* in_sizes, int n_in,
                              void* d_out, int out_size) {
    const float* pb  = (const float*)d_in[0];   // pred_beta    (N,1)
    const float* cc  = (const float*)d_in[1];   // pred_ccoords (N,2)
    const float* pe  = (const float*)d_in[2];   // pred_energy  (N,1)
    const float* pp  = (const float*)d_in[3];   // pred_pos     (N,2)
    const float* pt  = (const float*)d_in[4];   // pred_time    (N,1)
    const float* pid = (const float*)d_in[5];   // pred_id      (N,6)
    const int*   tix = (const int*)  d_in[6];   // t_idx        (N,1)
    const float* te  = (const float*)d_in[7];   // t_energy     (N,1)
    const float* tp  = (const float*)d_in[8];   // t_pos        (N,2)
    const float* tt  = (const float*)d_in[9];   // t_time       (N,1)
    // d_in[10] = t_pid, unused by the reference loss

    int n = in_sizes[0];

    k_hits<<<(n + 255) / 256, 256>>>(pb, cc, pe, pp, pt, pid, tix, te, tp, tt, n);
    k_pairs<<<(n + HPB - 1) / HPB, KOBJ>>>((float*)d_out, n, out_size);
}